// round 8
// baseline (speedup 1.0000x reference)
#include <cuda_runtime.h>

// ---------------------------------------------------------------------------
// SlayerNet forward:
//   x (64,100,2,32,32) -> conv1(5x5,pad2)+sumpool4*p1 -> PSP+spike scan (T=100)
//   -> conv2(3x3,pad1)+sumpool2*p2 -> PSP+spike scan -> dense (2,8,4,4)
//   out (64,100,2) float32
//
// conv+pool are linear, so they are folded into "effective" kernels:
//   stage1: 8x8 window, stride 4, pad 2 (Weff1[co][ci][u][v], u,v in 0..7)
//   stage2: 4x4 window, stride 2, pad 1 (Weff2[co][ci][u][v], u,v in 0..3)
// ---------------------------------------------------------------------------

#define TT   100
#define NB   64
#define NE1  16384   // 64 batches * 256 stage-1 elements (4,8,8)
#define NE2  8192    // 64 batches * 128 stage-2 elements (8,4,4)

// exp(-1/10) rounded to f32 (matches jnp.asarray(np.exp(-0.1), f32))
#define DECAY_F 0.9048374180359595f

// scratch (device globals: no allocations allowed)
__device__ float  g_u1[TT * NE1];          // pre-spike stage1 potentials, [t][n*256+e]
__device__ float  g_s1[TT * NE1];          // stage1 spikes
__device__ float  g_u2[TT * NE2];          // [t][n*128+e]
__device__ float  g_s2[TT * NE2];
__device__ float4 g_w1eff[2 * 8 * 8];      // [ci][u][v] -> (co0,co1,co2,co3)
__device__ float2 g_w2eff[4 * 4 * 4 * 4];  // [ci][u][v][pair] -> (co2p, co2p+1)

// ---- packed f32x2 helpers (Blackwell FFMA2 path, PTX-only) ----------------
__device__ __forceinline__ unsigned long long pk2(float x) {
    unsigned int b = __float_as_uint(x);
    unsigned long long r;
    asm("mov.b64 %0, {%1, %1};" : "=l"(r) : "r"(b));
    return r;
}
__device__ __forceinline__ void fma2(unsigned long long& acc,
                                     unsigned long long a,
                                     unsigned long long b) {
    asm("fma.rn.f32x2 %0, %1, %2, %0;" : "+l"(acc) : "l"(a), "l"(b));
}
__device__ __forceinline__ void unpk2(unsigned long long v, float& lo, float& hi) {
    unsigned int l, h;
    asm("mov.b64 {%0, %1}, %2;" : "=r"(l), "=r"(h) : "l"(v));
    lo = __uint_as_float(l);
    hi = __uint_as_float(h);
}

// ---------------------------------------------------------------------------
// K0: build effective conv+pool kernels (tiny, one block)
// ---------------------------------------------------------------------------
__global__ void prep_kernel(const float* __restrict__ w1,
                            const float* __restrict__ w2) {
    int tid = threadIdx.x;  // 128 threads
    // Weff1: 2 ci * 8 u * 8 v = 128 entries, float4 over co
    if (tid < 128) {
        int v = tid & 7, u = (tid >> 3) & 7, ci = tid >> 6;
        int ky0 = max(0, u - 3), ky1 = min(4, u);
        int kx0 = max(0, v - 3), kx1 = min(4, v);
        float acc[4];
        #pragma unroll
        for (int co = 0; co < 4; co++) {
            float s = 0.f;
            for (int ky = ky0; ky <= ky1; ky++)
                for (int kx = kx0; kx <= kx1; kx++)
                    s += w1[((co * 2 + ci) * 5 + ky) * 5 + kx];
            acc[co] = s;
        }
        g_w1eff[tid] = make_float4(acc[0], acc[1], acc[2], acc[3]);
    }
    // Weff2: 4 ci * 4 u * 4 v * 4 co-pairs = 256 entries
    for (int i = tid; i < 256; i += 128) {
        int pair = i & 3, v = (i >> 2) & 3, u = (i >> 4) & 3, ci = i >> 6;
        int ky0 = max(0, u - 1), ky1 = min(2, u);
        int kx0 = max(0, v - 1), kx1 = min(2, v);
        float s0 = 0.f, s1 = 0.f;
        for (int ky = ky0; ky <= ky1; ky++)
            for (int kx = kx0; kx <= kx1; kx++) {
                s0 += w2[(((2 * pair)     * 4 + ci) * 3 + ky) * 3 + kx];
                s1 += w2[(((2 * pair + 1) * 4 + ci) * 3 + ky) * 3 + kx];
            }
        g_w2eff[i] = make_float2(s0, s1);
    }
}

// ---------------------------------------------------------------------------
// K1: conv1eff per frame.  One block = one (n,t) frame, 64 threads = 64
// pooled windows (8x8).  Each thread accumulates all 4 output channels via
// packed f32x2 FMAs.  x tile held zero-padded in SMEM so window rows are
// 16B-aligned float4 loads.
// ---------------------------------------------------------------------------
__global__ __launch_bounds__(64) void conv1_kernel(const float* __restrict__ x,
                                                   const float* __restrict__ pool1p) {
    __shared__ __align__(16) float sx[2 * 36 * 36];  // pad-2 halo, zeroed
    __shared__ float4 sw[128];                        // Weff1
    const int tid = threadIdx.x;
    const int f = blockIdx.x;
    const int n = f / 100, t = f - n * 100;

    for (int i = tid; i < 128; i += 64) sw[i] = g_w1eff[i];
    for (int i = tid; i < 2 * 36 * 36; i += 64) sx[i] = 0.f;
    __syncthreads();

    const float4* xg = (const float4*)(x + (size_t)f * 2048);
    for (int i4 = tid; i4 < 512; i4 += 64) {
        float4 v = xg[i4];
        int ci = i4 >> 8, rem = i4 & 255, y = rem >> 3, xq = rem & 7;
        float* d = &sx[(ci * 36 + y + 2) * 36 + 4 * xq + 2];
        d[0] = v.x; d[1] = v.y; d[2] = v.z; d[3] = v.w;
    }
    __syncthreads();

    const int px = tid & 7, py = tid >> 3;
    unsigned long long acc01 = 0ull, acc23 = 0ull;
    #pragma unroll
    for (int ci = 0; ci < 2; ci++) {
        #pragma unroll
        for (int u = 0; u < 8; u++) {
            const float* row = &sx[(ci * 36 + py * 4 + u) * 36 + px * 4];
            float4 r0 = *(const float4*)row;
            float4 r1 = *(const float4*)(row + 4);
            float xv[8] = {r0.x, r0.y, r0.z, r0.w, r1.x, r1.y, r1.z, r1.w};
            #pragma unroll
            for (int v = 0; v < 8; v++) {
                const ulonglong2 w = *(const ulonglong2*)&sw[(ci * 8 + u) * 8 + v];
                unsigned long long xx = pk2(xv[v]);
                fma2(acc01, xx, w.x);
                fma2(acc23, xx, w.y);
            }
        }
    }
    const float p1 = *pool1p;
    float a0, a1, a2, a3;
    unpk2(acc01, a0, a1);
    unpk2(acc23, a2, a3);
    const int ob = t * NE1 + n * 256 + py * 8 + px;  // e = co*64 + py*8 + px
    g_u1[ob]       = a0 * p1;
    g_u1[ob + 64]  = a1 * p1;
    g_u1[ob + 128] = a2 * p1;
    g_u1[ob + 192] = a3 * p1;
}

// ---------------------------------------------------------------------------
// K2/K4: PSP + threshold/refractory scans.  t-major layout -> every timestep
// is one fully coalesced load/store per warp; loads are independent of the
// recurrence so unrolling lets ptxas batch them ahead.
// ---------------------------------------------------------------------------
__global__ void scan1_kernel() {
    const int g = blockIdx.x * blockDim.x + threadIdx.x;  // < NE1
    float psp = 0.f, r = 0.f;
    #pragma unroll 5
    for (int t = 0; t < TT; t++) {
        float ut = g_u1[t * NE1 + g];
        psp = fmaf(DECAY_F, psp, ut);
        float sp = (psp - r >= 1.0f) ? 1.0f : 0.0f;
        g_s1[t * NE1 + g] = sp;
        r = DECAY_F * (r + sp);
    }
}

__global__ void scan2_kernel() {
    const int g = blockIdx.x * blockDim.x + threadIdx.x;  // < NE2
    float psp = 0.f, r = 0.f;
    #pragma unroll 5
    for (int t = 0; t < TT; t++) {
        float ut = g_u2[t * NE2 + g];
        psp = fmaf(DECAY_F, psp, ut);
        float sp = (psp - r >= 1.0f) ? 1.0f : 0.0f;
        g_s2[t * NE2 + g] = sp;
        r = DECAY_F * (r + sp);
    }
}

// ---------------------------------------------------------------------------
// K3: conv2eff per frame.  One block = one frame, 64 threads = 16 windows x
// 4 co-pairs, packed f32x2 accumulators.
// ---------------------------------------------------------------------------
__global__ __launch_bounds__(64) void conv2_kernel(const float* __restrict__ pool2p) {
    __shared__ float  ss[4 * 10 * 10];  // pad-1 halo
    __shared__ float2 sw[256];
    const int tid = threadIdx.x;
    const int f = blockIdx.x;
    const int n = f / 100, t = f - n * 100;

    for (int i = tid; i < 256; i += 64) sw[i] = g_w2eff[i];
    for (int i = tid; i < 400; i += 64) ss[i] = 0.f;
    __syncthreads();

    const float* sb = &g_s1[t * NE1 + n * 256];
    for (int i = tid; i < 256; i += 64) {
        int ci = i >> 6, y = (i >> 3) & 7, xc = i & 7;
        ss[(ci * 10 + y + 1) * 10 + xc + 1] = sb[i];
    }
    __syncthreads();

    const int p = tid >> 4;        // co-pair 0..3
    const int w = tid & 15;        // window 0..15
    const int py = w >> 2, px = w & 3;
    unsigned long long acc = 0ull;
    #pragma unroll
    for (int ci = 0; ci < 4; ci++) {
        #pragma unroll
        for (int u = 0; u < 4; u++) {
            const float* row = &ss[(ci * 10 + py * 2 + u) * 10 + px * 2];
            #pragma unroll
            for (int v = 0; v < 4; v++) {
                unsigned long long wv =
                    *(const unsigned long long*)&sw[((ci * 4 + u) * 4 + v) * 4 + p];
                fma2(acc, pk2(row[v]), wv);
            }
        }
    }
    const float p2 = *pool2p;
    float lo, hi;
    unpk2(acc, lo, hi);
    const int ob = t * NE2 + n * 128 + p * 32 + w;  // e = co*16 + py*4 + px
    g_u2[ob]      = lo * p2;
    g_u2[ob + 16] = hi * p2;
}

// ---------------------------------------------------------------------------
// K5: dense layer. one warp per (n,t): 128-element dot against both output
// rows of lin_w, shfl reduce.
// ---------------------------------------------------------------------------
__global__ __launch_bounds__(256) void out_kernel(const float* __restrict__ lin,
                                                  float* __restrict__ out) {
    const int warp = (blockIdx.x * 256 + threadIdx.x) >> 5;
    const int lane = threadIdx.x & 31;
    if (warp >= NB * TT) return;
    const int n = warp / 100, t = warp - n * 100;
    const float* sb = &g_s2[t * NE2 + n * 128];
    float a0 = 0.f, a1 = 0.f;
    #pragma unroll
    for (int k = 0; k < 4; k++) {
        int e = lane + k * 32;
        float sv = sb[e];
        a0 = fmaf(sv, lin[e],       a0);
        a1 = fmaf(sv, lin[128 + e], a1);
    }
    #pragma unroll
    for (int off = 16; off; off >>= 1) {
        a0 += __shfl_down_sync(0xffffffffu, a0, off);
        a1 += __shfl_down_sync(0xffffffffu, a1, off);
    }
    if (lane == 0) {
        out[(n * 100 + t) * 2]     = a0;
        out[(n * 100 + t) * 2 + 1] = a1;
    }
}

// ---------------------------------------------------------------------------
extern "C" void kernel_launch(void* const* d_in, const int* in_sizes, int n_in,
                              void* d_out, int out_size) {
    const float* x    = (const float*)d_in[0];  // (64,100,2,32,32)
    const float* w1   = (const float*)d_in[1];  // (4,2,5,5)
    const float* w2   = (const float*)d_in[2];  // (8,4,3,3)
    const float* lin  = (const float*)d_in[3];  // (2,8,4,4)
    const float* p1   = (const float*)d_in[4];  // scalar
    const float* p2   = (const float*)d_in[5];  // scalar
    float* out = (float*)d_out;                 // (64,100,2)

    prep_kernel<<<1, 128>>>(w1, w2);
    conv1_kernel<<<NB * TT, 64>>>(x, p1);
    scan1_kernel<<<NE1 / 256, 256>>>();
    conv2_kernel<<<NB * TT, 64>>>(p2);
    scan2_kernel<<<NE2 / 256, 256>>>();
    out_kernel<<<(NB * TT + 7) / 8, 256>>>(lin, out);
}